// round 9
// baseline (speedup 1.0000x reference)
#include <cuda_runtime.h>

#define EPS 1e-5f

// Fixed problem capacities (N=100000, E=1600000 per the dataset)
#define MAXN   100000
#define MAXN2  50000
#define MAXN3  25000
#define MAXN4  8340

// ---------------- scratch (static device globals; no allocation) ----------------
// Only referenced INSIDE kernels (never passed as kernel args from host code).
__device__ int    g_deg1[MAXN];
__device__ int    g_deg2[MAXN2];
__device__ int    g_deg3[MAXN3];
__device__ int    g_deg4[MAXN4];
__device__ float  g_dis1[MAXN];
__device__ float  g_dis2[MAXN2];
__device__ float  g_dis3[MAXN3];
__device__ float  g_dis4[MAXN4];
__device__ float  g_y[MAXN];           // dis1[i]*x[i]
__device__ float  g_s[MAXN];           // scalar neighbor sums (layer 1)
__device__ float  g_mean[4][64];       // BN stats per layer
__device__ float  g_var[4][64];
__device__ float  g_constrow[10];      // output row for padded nodes
__device__ __align__(16) float g_a[MAXN2 * 64];    // pooled (pre-BN)
__device__ __align__(16) float g_b[MAXN2 * 64];    // bn_relu output
__device__ __align__(16) float g_xw[MAXN2 * 64];   // x @ W for current layer
__device__ __align__(16) float g_msg[MAXN2 * 64];  // conv output accumulator

// ---------------- init (idempotent reset) ----------------
__global__ void k_init() {
    int i = blockIdx.x * blockDim.x + threadIdx.x;
    if (i < MAXN)  { g_deg1[i] = 0; g_s[i] = 0.f; }
    if (i < MAXN2) g_deg2[i] = 0;
    if (i < MAXN3) g_deg3[i] = 0;
    if (i < MAXN4) g_deg4[i] = 0;
}

// ---------------- degree pass: all 4 levels from original edges (int32!) ----------
__global__ void k_deg(const int* __restrict__ src,
                      const int* __restrict__ dst, int E) {
    int e = blockIdx.x * blockDim.x + threadIdx.x;
    if (e >= E) return;
    int s = src[e];
    int d = dst[e];
    if ((unsigned)s >= MAXN || (unsigned)d >= MAXN) return;  // defensive
    atomicAdd(&g_deg1[d], 1);
    if (((s | d) & 1) == 0)  atomicAdd(&g_deg2[d >> 1], 1);
    if (((s | d) & 3) == 0)  atomicAdd(&g_deg3[d >> 2], 1);
    if ((s % 12 == 0) && (d % 12 == 0)) atomicAdd(&g_deg4[d / 12], 1);
}

// ---------------- node pass: dis arrays + y ----------------
__global__ void k_node(const float* __restrict__ x, int N1, int N2, int N3, int N4) {
    int i = blockIdx.x * blockDim.x + threadIdx.x;
    if (i < N1) {
        float di = rsqrtf((float)g_deg1[i] + 1.f);
        g_dis1[i] = di;
        g_y[i] = di * x[i];
    }
    if (i < N2) g_dis2[i] = rsqrtf((float)g_deg2[i] + 1.f);
    if (i < N3) g_dis3[i] = rsqrtf((float)g_deg3[i] + 1.f);
    if (i < N4) g_dis4[i] = rsqrtf((float)g_deg4[i] + 1.f);
}

// ---------------- layer-1 scalar aggregation (exact rank-1 identity) ----------------
__global__ void k_sagg(const int* __restrict__ src,
                       const int* __restrict__ dst, int E) {
    int e = blockIdx.x * blockDim.x + threadIdx.x;
    if (e >= E) return;
    int s = src[e];
    int d = dst[e];
    if ((unsigned)s >= MAXN || (unsigned)d >= MAXN) return;
    atomicAdd(&g_s[d], g_y[s]);
}

// ---------------- pooled1[p,c] = mean(conv1[2p],conv1[2p+1])[c] -> g_a ------------
// conv1[i,c] = t_i*W1[c] + b1[c],  t_i = dis1_i*(sum_in + dis1_i*x_i)
__global__ void k_pool1(const float* __restrict__ x, const float* __restrict__ W1,
                        const float* __restrict__ b1, int N1, int N2) {
    int idx = blockIdx.x * blockDim.x + threadIdx.x;
    int p = idx >> 6, c = idx & 63;
    if (p >= N2) return;
    int i0 = 2 * p;
    float d0 = g_dis1[i0];
    float t = d0 * (g_s[i0] + d0 * x[i0]);
    int i1 = i0 + 1;
    if (i1 < N1) {
        float d1 = g_dis1[i1];
        t += d1 * (g_s[i1] + d1 * x[i1]);
    }
    g_a[idx] = 0.5f * t * W1[c] + b1[c];
}

// ---------------- BN stats over g_a: one block per channel, deterministic ----------
__global__ void k_stats(int N, int l) {
    __shared__ float sh1[256], sh2[256];
    int c = blockIdx.x;  // 0..63
    float s1 = 0.f, s2 = 0.f;
    for (int r = threadIdx.x; r < N; r += 256) {
        float v = g_a[(size_t)r * 64 + c];
        s1 += v;
        s2 += v * v;
    }
    sh1[threadIdx.x] = s1; sh2[threadIdx.x] = s2;
    __syncthreads();
    for (int o = 128; o; o >>= 1) {
        if (threadIdx.x < o) {
            sh1[threadIdx.x] += sh1[threadIdx.x + o];
            sh2[threadIdx.x] += sh2[threadIdx.x + o];
        }
        __syncthreads();
    }
    if (threadIdx.x == 0) {
        float m = sh1[0] / (float)N;
        g_mean[l][c] = m;
        g_var[l][c] = sh2[0] / (float)N - m * m;
    }
}

// ---------------- BN apply + ReLU: g_a -> g_b ----------------
__global__ void k_bnrelu(int N, int l, const float* __restrict__ g,
                         const float* __restrict__ be) {
    int idx = blockIdx.x * blockDim.x + threadIdx.x;
    if (idx >= N * 64) return;
    int c = idx & 63;
    float m = g_mean[l][c];
    float v = g_var[l][c];
    float val = (g_a[idx] - m) * rsqrtf(v + EPS) * g[c] + be[c];
    g_b[idx] = fmaxf(val, 0.f);
}

// ---------------- plain GEMM + self-loop/bias epilogue: g_b -> g_xw, g_msg --------
template <int L>
__global__ void k_gemm(const float* __restrict__ W, const float* __restrict__ b, int N) {
    __shared__ float Ws[64 * 64];
    __shared__ float xs[32][65];
    const float* dis = (L == 2) ? g_dis2 : (L == 3) ? g_dis3 : g_dis4;
    int tid = threadIdx.x;
    for (int i = tid; i < 4096; i += 256) Ws[i] = W[i];
    int row0 = blockIdx.x * 32;
    for (int i = tid; i < 2048; i += 256) {
        int r = i >> 6, k = i & 63;
        int row = row0 + r;
        float v = 0.f;
        if (row < N) v = g_b[(size_t)row * 64 + k];
        xs[r][k] = v;
    }
    __syncthreads();
    int c = tid & 63;
    int rq = tid >> 6;
    float acc[8] = {0.f, 0.f, 0.f, 0.f, 0.f, 0.f, 0.f, 0.f};
    #pragma unroll
    for (int k = 0; k < 64; k++) {
        float w = Ws[k * 64 + c];
        #pragma unroll
        for (int j = 0; j < 8; j++) acc[j] = fmaf(xs[rq * 8 + j][k], w, acc[j]);
    }
    float bc = b[c];
    #pragma unroll
    for (int j = 0; j < 8; j++) {
        int row = row0 + rq * 8 + j;
        if (row < N) {
            float di = dis[row];
            g_xw[(size_t)row * 64 + c] = acc[j];
            g_msg[(size_t)row * 64 + c] = fmaf(di * di, acc[j], bc);
        }
    }
}

// ---------------- edge aggregation straight from original edges ----------------
// mask: s%D==0 && d%D==0; remap s/D, d/D (reference's ew-masking, literally)
template <int D, int L>
__global__ void k_econv(const int* __restrict__ src,
                        const int* __restrict__ dst, int E) {
    const float* dis = (L == 2) ? g_dis2 : (L == 3) ? g_dis3 : g_dis4;
    int gtid = blockIdx.x * blockDim.x + threadIdx.x;
    int lane = gtid & 15;
    int grp  = gtid >> 4;
    int step = (gridDim.x * blockDim.x) >> 4;
    for (int e = grp; e < E; e += step) {
        int s = src[e];
        int d = dst[e];
        if ((unsigned)s >= MAXN || (unsigned)d >= MAXN) continue;
        if ((s % D) || (d % D)) continue;
        int ss = s / D, dd = d / D;
        float coef = dis[ss] * dis[dd];
        const float* ps = g_xw + (size_t)ss * 64 + lane * 4;
        float* pd = g_msg + (size_t)dd * 64 + lane * 4;
        atomicAdd(pd + 0, ps[0] * coef);
        atomicAdd(pd + 1, ps[1] * coef);
        atomicAdd(pd + 2, ps[2] * coef);
        atomicAdd(pd + 3, ps[3] * coef);
    }
}

// ---------------- pool g_msg -> g_a (mean over stride groups, zero-padded) --------
__global__ void k_pool(int Nin, int Nout, int S) {
    int idx = blockIdx.x * blockDim.x + threadIdx.x;
    int p = idx >> 6, c = idx & 63;
    if (p >= Nout) return;
    float acc = 0.f;
    int base = p * S;
    for (int q = 0; q < S; q++) {
        int r = base + q;
        if (r < Nin) acc += g_msg[(size_t)r * 64 + c];
    }
    g_a[idx] = acc / (float)S;
}

// ---------------- constant output row for padded nodes ----------------
__global__ void k_constrow(const float* __restrict__ fcb1,
                           const float* __restrict__ fcW2,
                           const float* __restrict__ fcb2) {
    int c = threadIdx.x;
    if (c < 10) {
        float acc = fcb2[c];
        for (int k = 0; k < 128; k++)
            acc = fmaf(fmaxf(0.f, fcb1[k]), fcW2[k * 10 + c], acc);
        g_constrow[c] = acc;
    }
}

// ---------------- FC head for the live rows (reads g_b, layer-4 bn output) --------
__global__ void k_fc(const float* __restrict__ fcW1, const float* __restrict__ fcb1,
                     const float* __restrict__ fcW2, const float* __restrict__ fcb2,
                     float* __restrict__ out, int N5) {
    __shared__ float W1s[64 * 128];
    __shared__ float W2s[128 * 10];
    __shared__ float xr[64];
    __shared__ float hb[128];
    int tid = threadIdx.x;  // 128 threads
    for (int i = tid; i < 8192; i += 128) W1s[i] = fcW1[i];
    for (int i = tid; i < 1280; i += 128) W2s[i] = fcW2[i];
    __syncthreads();
    int r0 = blockIdx.x * 16;
    for (int rr = 0; rr < 16; rr++) {
        int row = r0 + rr;
        if (row >= N5) break;  // uniform across block
        if (tid < 64) xr[tid] = g_b[(size_t)row * 64 + tid];
        __syncthreads();
        float h = fcb1[tid];
        #pragma unroll
        for (int k = 0; k < 64; k++) h = fmaf(xr[k], W1s[k * 128 + tid], h);
        hb[tid] = fmaxf(0.f, h);
        __syncthreads();
        if (tid < 10) {
            float acc = fcb2[tid];
            #pragma unroll 8
            for (int k = 0; k < 128; k++) acc = fmaf(hb[k], W2s[k * 10 + tid], acc);
            out[(size_t)row * 10 + tid] = acc;
        }
        __syncthreads();
    }
}

// ---------------- constant fill for padded rows ----------------
__global__ void k_fill(float* __restrict__ out, int N0, int N5) {
    long long total = (long long)(N0 - N5) * 10;
    long long idx = (long long)blockIdx.x * blockDim.x + threadIdx.x;
    if (idx < total) {
        int j = (int)(idx % 10);
        long long r = N5 + idx / 10;
        out[r * 10 + j] = g_constrow[j];
    }
}

// ---------------- launch ----------------
extern "C" void kernel_launch(void* const* d_in, const int* in_sizes, int n_in,
                              void* d_out, int out_size) {
    const float* x    = (const float*)d_in[0];
    const float* W1   = (const float*)d_in[1];
    const float* b1   = (const float*)d_in[2];
    const float* g1   = (const float*)d_in[3];
    const float* be1  = (const float*)d_in[4];
    const float* W2   = (const float*)d_in[5];
    const float* b2   = (const float*)d_in[6];
    const float* g2   = (const float*)d_in[7];
    const float* be2  = (const float*)d_in[8];
    const float* W3   = (const float*)d_in[9];
    const float* b3   = (const float*)d_in[10];
    const float* g3   = (const float*)d_in[11];
    const float* be3  = (const float*)d_in[12];
    const float* W4   = (const float*)d_in[13];
    const float* b4   = (const float*)d_in[14];
    const float* g4   = (const float*)d_in[15];
    const float* be4  = (const float*)d_in[16];
    const float* fcW1 = (const float*)d_in[17];
    const float* fcb1 = (const float*)d_in[18];
    const float* fcW2 = (const float*)d_in[19];
    const float* fcb2 = (const float*)d_in[20];
    // JAX x64 is disabled in the reference env: "int64" arrays are int32.
    const int* src = (const int*)d_in[21];
    const int* dst = (const int*)d_in[22];

    int N0 = in_sizes[0];
    if (N0 > MAXN) N0 = MAXN;
    int E  = in_sizes[21];
    int N2 = (N0 + 1) / 2;
    int N3 = (N2 + 1) / 2;
    int N4 = (N3 + 2) / 3;
    int N5 = (N4 + 2) / 3;
    float* out = (float*)d_out;

    k_init<<<(MAXN + 255) / 256, 256>>>();
    k_deg<<<(E + 255) / 256, 256>>>(src, dst, E);
    k_node<<<(N0 + 255) / 256, 256>>>(x, N0, N2, N3, N4);
    k_sagg<<<(E + 255) / 256, 256>>>(src, dst, E);

    // layer 1: conv (rank-1, exact) + pool -> g_a ; BN -> g_b
    k_pool1<<<(N2 * 64 + 255) / 256, 256>>>(x, W1, b1, N0, N2);
    k_stats<<<64, 256>>>(N2, 0);
    k_bnrelu<<<(N2 * 64 + 255) / 256, 256>>>(N2, 0, g1, be1);

    // layer 2
    k_gemm<2><<<(N2 + 31) / 32, 256>>>(W2, b2, N2);
    k_econv<2, 2><<<2048, 256>>>(src, dst, E);
    k_pool<<<(N3 * 64 + 255) / 256, 256>>>(N2, N3, 2);
    k_stats<<<64, 256>>>(N3, 1);
    k_bnrelu<<<(N3 * 64 + 255) / 256, 256>>>(N3, 1, g2, be2);

    // layer 3
    k_gemm<3><<<(N3 + 31) / 32, 256>>>(W3, b3, N3);
    k_econv<4, 3><<<2048, 256>>>(src, dst, E);
    k_pool<<<(N4 * 64 + 255) / 256, 256>>>(N3, N4, 3);
    k_stats<<<64, 256>>>(N4, 2);
    k_bnrelu<<<(N4 * 64 + 255) / 256, 256>>>(N4, 2, g3, be3);

    // layer 4
    k_gemm<4><<<(N4 + 31) / 32, 256>>>(W4, b4, N4);
    k_econv<12, 4><<<2048, 256>>>(src, dst, E);
    k_pool<<<(N5 * 64 + 255) / 256, 256>>>(N4, N5, 3);
    k_stats<<<64, 256>>>(N5, 3);
    k_bnrelu<<<(N5 * 64 + 255) / 256, 256>>>(N5, 3, g4, be4);

    // head
    k_constrow<<<1, 32>>>(fcb1, fcW2, fcb2);
    k_fc<<<(N5 + 15) / 16, 128>>>(fcW1, fcb1, fcW2, fcb2, out, N5);
    long long fillN = (long long)(N0 - N5) * 10;
    k_fill<<<(int)((fillN + 255) / 256), 256>>>(out, N0, N5);
}

// round 10
// speedup vs baseline: 1.4780x; 1.4780x over previous
#include <cuda_runtime.h>

#define EPS 1e-5f

// Fixed problem capacities (N=100000, E=1600000 per the dataset)
#define MAXN   100000
#define MAXN2  50000
#define MAXN3  25000
#define MAXN4  8340
#define MAXE   1600000

// ---------------- scratch (static device globals; no allocation) ----------------
// Only referenced INSIDE kernels (never passed as kernel args from host code).
__device__ int    g_deg1[MAXN];
__device__ int    g_deg2[MAXN2];
__device__ int    g_deg3[MAXN3];
__device__ int    g_deg4[MAXN4];
__device__ float  g_dis1[MAXN];
__device__ float  g_dis2[MAXN2];
__device__ float  g_dis3[MAXN3];
__device__ float  g_dis4[MAXN4];
__device__ float  g_y[MAXN];           // dis1[i]*x[i]
__device__ float  g_s[MAXN];           // scalar neighbor sums (layer 1)
__device__ float  g_sc[4][64];         // fused BN scale per layer
__device__ float  g_sh[4][64];         // fused BN shift per layer
__device__ float  g_constrow[10];      // output row for padded nodes
__device__ int    g_cnt[3];            // compacted edge counts
__device__ __align__(16) int2  g_e2[MAXE];
__device__ __align__(16) int2  g_e3[MAXE];
__device__ __align__(16) int2  g_e4[MAXE];
__device__ __align__(16) float g_a[MAXN2 * 64];    // pooled (pre-BN)
__device__ __align__(16) float g_xw[MAXN2 * 64];   // x @ W for current layer
__device__ __align__(16) float g_msg[MAXN2 * 64];  // conv output accumulator

// ---------------- init (idempotent reset) ----------------
__global__ void k_init() {
    int i = blockIdx.x * blockDim.x + threadIdx.x;
    if (i < MAXN)  { g_deg1[i] = 0; g_s[i] = 0.f; }
    if (i < MAXN2) g_deg2[i] = 0;
    if (i < MAXN3) g_deg3[i] = 0;
    if (i < MAXN4) g_deg4[i] = 0;
    if (i < 3)     g_cnt[i] = 0;
}

// ---------------- degree pass + edge compaction (block-staged) ----------------
__global__ void k_deg(const int* __restrict__ src,
                      const int* __restrict__ dst, int E) {
    __shared__ int  sc[3];
    __shared__ int  sb[3];
    __shared__ int2 st[3][256];
    int tid = threadIdx.x;
    if (tid < 3) sc[tid] = 0;
    __syncthreads();

    int e = blockIdx.x * blockDim.x + tid;
    if (e < E) {
        int s = src[e];
        int d = dst[e];
        if ((unsigned)s < MAXN && (unsigned)d < MAXN) {
            atomicAdd(&g_deg1[d], 1);
            if (((s | d) & 1) == 0) {
                int p = atomicAdd(&sc[0], 1);
                st[0][p] = make_int2(s >> 1, d >> 1);
                atomicAdd(&g_deg2[d >> 1], 1);
            }
            if (((s | d) & 3) == 0) {
                int p = atomicAdd(&sc[1], 1);
                st[1][p] = make_int2(s >> 2, d >> 2);
                atomicAdd(&g_deg3[d >> 2], 1);
            }
            if ((s % 12 == 0) && (d % 12 == 0)) {
                int p = atomicAdd(&sc[2], 1);
                st[2][p] = make_int2(s / 12, d / 12);
                atomicAdd(&g_deg4[d / 12], 1);
            }
        }
    }
    __syncthreads();
    if (tid < 3) sb[tid] = atomicAdd(&g_cnt[tid], sc[tid]);
    __syncthreads();
    #pragma unroll
    for (int l = 0; l < 3; l++) {
        int n = sc[l];
        int2* dstp = (l == 0) ? g_e2 : (l == 1) ? g_e3 : g_e4;
        int base = sb[l];
        for (int i = tid; i < n; i += blockDim.x) {
            int idx = base + i;
            if (idx < MAXE) dstp[idx] = st[l][i];
        }
    }
}

// ---------------- node pass: dis arrays + y ----------------
__global__ void k_node(const float* __restrict__ x, int N1, int N2, int N3, int N4) {
    int i = blockIdx.x * blockDim.x + threadIdx.x;
    if (i < N1) {
        float di = rsqrtf((float)g_deg1[i] + 1.f);
        g_dis1[i] = di;
        g_y[i] = di * x[i];
    }
    if (i < N2) g_dis2[i] = rsqrtf((float)g_deg2[i] + 1.f);
    if (i < N3) g_dis3[i] = rsqrtf((float)g_deg3[i] + 1.f);
    if (i < N4) g_dis4[i] = rsqrtf((float)g_deg4[i] + 1.f);
}

// ---------------- layer-1 scalar aggregation (exact rank-1 identity) ----------------
__global__ void k_sagg(const int* __restrict__ src,
                       const int* __restrict__ dst, int E) {
    int e = blockIdx.x * blockDim.x + threadIdx.x;
    if (e >= E) return;
    int s = src[e];
    int d = dst[e];
    if ((unsigned)s >= MAXN || (unsigned)d >= MAXN) return;
    atomicAdd(&g_s[d], g_y[s]);
}

// ---------------- pooled1[p,c] = mean(conv1[2p],conv1[2p+1])[c] -> g_a ------------
__global__ void k_pool1(const float* __restrict__ x, const float* __restrict__ W1,
                        const float* __restrict__ b1, int N1, int N2) {
    int idx = blockIdx.x * blockDim.x + threadIdx.x;
    int p = idx >> 6, c = idx & 63;
    if (p >= N2) return;
    int i0 = 2 * p;
    float d0 = g_dis1[i0];
    float t = d0 * (g_s[i0] + d0 * x[i0]);
    int i1 = i0 + 1;
    if (i1 < N1) {
        float d1 = g_dis1[i1];
        t += d1 * (g_s[i1] + d1 * x[i1]);
    }
    g_a[idx] = 0.5f * t * W1[c] + b1[c];
}

// ---------------- BN stats over g_a -> fused scale/shift (deterministic) ----------
__global__ void k_stats(int N, int l, const float* __restrict__ g,
                        const float* __restrict__ be) {
    __shared__ float sh1[256], sh2[256];
    int c = blockIdx.x;  // 0..63
    float s1 = 0.f, s2 = 0.f;
    for (int r = threadIdx.x; r < N; r += 256) {
        float v = g_a[(size_t)r * 64 + c];
        s1 += v;
        s2 += v * v;
    }
    sh1[threadIdx.x] = s1; sh2[threadIdx.x] = s2;
    __syncthreads();
    for (int o = 128; o; o >>= 1) {
        if (threadIdx.x < o) {
            sh1[threadIdx.x] += sh1[threadIdx.x + o];
            sh2[threadIdx.x] += sh2[threadIdx.x + o];
        }
        __syncthreads();
    }
    if (threadIdx.x == 0) {
        float m = sh1[0] / (float)N;
        float v = sh2[0] / (float)N - m * m;
        float sc = rsqrtf(v + EPS) * g[c];
        g_sc[l][c] = sc;
        g_sh[l][c] = be[c] - m * sc;
    }
}

// ---------------- fused BN-ReLU + GEMM + self-loop/bias epilogue ----------------
// input rows are relu(g_a[row,k]*sc[k]+sh[k]); writes g_xw, g_msg
template <int L>
__global__ void k_gemm(const float* __restrict__ W, const float* __restrict__ b, int N) {
    __shared__ float Ws[64 * 64];
    __shared__ float xs[32][65];
    const float* dis = (L == 2) ? g_dis2 : (L == 3) ? g_dis3 : g_dis4;
    int tid = threadIdx.x;
    for (int i = tid; i < 4096; i += 256) Ws[i] = W[i];
    int row0 = blockIdx.x * 32;
    for (int i = tid; i < 2048; i += 256) {
        int r = i >> 6, k = i & 63;
        int row = row0 + r;
        float v = 0.f;
        if (row < N)
            v = fmaxf(0.f, fmaf(g_a[(size_t)row * 64 + k], g_sc[L - 2][k], g_sh[L - 2][k]));
        xs[r][k] = v;
    }
    __syncthreads();
    int c = tid & 63;
    int rq = tid >> 6;
    float acc[8] = {0.f, 0.f, 0.f, 0.f, 0.f, 0.f, 0.f, 0.f};
    #pragma unroll
    for (int k = 0; k < 64; k++) {
        float w = Ws[k * 64 + c];
        #pragma unroll
        for (int j = 0; j < 8; j++) acc[j] = fmaf(xs[rq * 8 + j][k], w, acc[j]);
    }
    float bc = b[c];
    #pragma unroll
    for (int j = 0; j < 8; j++) {
        int row = row0 + rq * 8 + j;
        if (row < N) {
            float di = dis[row];
            g_xw[(size_t)row * 64 + c] = acc[j];
            g_msg[(size_t)row * 64 + c] = fmaf(di * di, acc[j], bc);
        }
    }
}

// ---------------- sparse aggregation over compacted lists, vector red -------------
template <int L>
__global__ void k_econv() {
    const int2*  el  = (L == 2) ? g_e2   : (L == 3) ? g_e3   : g_e4;
    const float* dis = (L == 2) ? g_dis2 : (L == 3) ? g_dis3 : g_dis4;
    int cnt = g_cnt[L - 2];
    if (cnt > MAXE) cnt = MAXE;
    int gtid = blockIdx.x * blockDim.x + threadIdx.x;
    int lane = gtid & 15;
    int grp  = gtid >> 4;
    int step = (gridDim.x * blockDim.x) >> 4;
    for (int e = grp; e < cnt; e += step) {
        int2 ed = el[e];
        float coef = dis[ed.x] * dis[ed.y];
        float4 v = *((const float4*)(g_xw + (size_t)ed.x * 64) + lane);
        float4* pd = (float4*)(g_msg + (size_t)ed.y * 64) + lane;
        asm volatile("red.global.add.v4.f32 [%0], {%1,%2,%3,%4};"
                     :: "l"(pd), "f"(v.x * coef), "f"(v.y * coef),
                        "f"(v.z * coef), "f"(v.w * coef)
                     : "memory");
    }
}

// ---------------- pool g_msg -> g_a (mean over stride groups, zero-padded) --------
__global__ void k_pool(int Nin, int Nout, int S) {
    int idx = blockIdx.x * blockDim.x + threadIdx.x;
    int p = idx >> 6, c = idx & 63;
    if (p >= Nout) return;
    float acc = 0.f;
    int base = p * S;
    for (int q = 0; q < S; q++) {
        int r = base + q;
        if (r < Nin) acc += g_msg[(size_t)r * 64 + c];
    }
    g_a[idx] = acc / (float)S;
}

// ---------------- constant output row for padded nodes ----------------
__global__ void k_constrow(const float* __restrict__ fcb1,
                           const float* __restrict__ fcW2,
                           const float* __restrict__ fcb2) {
    int c = threadIdx.x;
    if (c < 10) {
        float acc = fcb2[c];
        for (int k = 0; k < 128; k++)
            acc = fmaf(fmaxf(0.f, fcb1[k]), fcW2[k * 10 + c], acc);
        g_constrow[c] = acc;
    }
}

// ---------------- FC head: applies layer-4 BN (l=3) on the fly --------------------
__global__ void k_fc(const float* __restrict__ fcW1, const float* __restrict__ fcb1,
                     const float* __restrict__ fcW2, const float* __restrict__ fcb2,
                     float* __restrict__ out, int N5) {
    __shared__ float W1s[64 * 128];
    __shared__ float W2s[128 * 10];
    __shared__ float xr[64];
    __shared__ float hb[128];
    int tid = threadIdx.x;  // 128 threads
    for (int i = tid; i < 8192; i += 128) W1s[i] = fcW1[i];
    for (int i = tid; i < 1280; i += 128) W2s[i] = fcW2[i];
    __syncthreads();
    int r0 = blockIdx.x * 16;
    for (int rr = 0; rr < 16; rr++) {
        int row = r0 + rr;
        if (row >= N5) break;  // uniform across block
        if (tid < 64)
            xr[tid] = fmaxf(0.f, fmaf(g_a[(size_t)row * 64 + tid],
                                      g_sc[3][tid], g_sh[3][tid]));
        __syncthreads();
        float h = fcb1[tid];
        #pragma unroll
        for (int k = 0; k < 64; k++) h = fmaf(xr[k], W1s[k * 128 + tid], h);
        hb[tid] = fmaxf(0.f, h);
        __syncthreads();
        if (tid < 10) {
            float acc = fcb2[tid];
            #pragma unroll 8
            for (int k = 0; k < 128; k++) acc = fmaf(hb[k], W2s[k * 10 + tid], acc);
            out[(size_t)row * 10 + tid] = acc;
        }
        __syncthreads();
    }
}

// ---------------- constant fill for padded rows ----------------
__global__ void k_fill(float* __restrict__ out, int N0, int N5) {
    long long total = (long long)(N0 - N5) * 10;
    long long idx = (long long)blockIdx.x * blockDim.x + threadIdx.x;
    if (idx < total) {
        int j = (int)(idx % 10);
        long long r = N5 + idx / 10;
        out[r * 10 + j] = g_constrow[j];
    }
}

// ---------------- launch ----------------
extern "C" void kernel_launch(void* const* d_in, const int* in_sizes, int n_in,
                              void* d_out, int out_size) {
    const float* x    = (const float*)d_in[0];
    const float* W1   = (const float*)d_in[1];
    const float* b1   = (const float*)d_in[2];
    const float* g1   = (const float*)d_in[3];
    const float* be1  = (const float*)d_in[4];
    const float* W2   = (const float*)d_in[5];
    const float* b2   = (const float*)d_in[6];
    const float* g2   = (const float*)d_in[7];
    const float* be2  = (const float*)d_in[8];
    const float* W3   = (const float*)d_in[9];
    const float* b3   = (const float*)d_in[10];
    const float* g3   = (const float*)d_in[11];
    const float* be3  = (const float*)d_in[12];
    const float* W4   = (const float*)d_in[13];
    const float* b4   = (const float*)d_in[14];
    const float* g4   = (const float*)d_in[15];
    const float* be4  = (const float*)d_in[16];
    const float* fcW1 = (const float*)d_in[17];
    const float* fcb1 = (const float*)d_in[18];
    const float* fcW2 = (const float*)d_in[19];
    const float* fcb2 = (const float*)d_in[20];
    // JAX x64 disabled: "int64" arrays are int32.
    const int* src = (const int*)d_in[21];
    const int* dst = (const int*)d_in[22];

    int N0 = in_sizes[0];
    if (N0 > MAXN) N0 = MAXN;
    int E  = in_sizes[21];
    if (E > MAXE) E = MAXE;
    int N2 = (N0 + 1) / 2;
    int N3 = (N2 + 1) / 2;
    int N4 = (N3 + 2) / 3;
    int N5 = (N4 + 2) / 3;
    float* out = (float*)d_out;

    k_init<<<(MAXN + 255) / 256, 256>>>();
    k_deg<<<(E + 255) / 256, 256>>>(src, dst, E);
    k_node<<<(N0 + 255) / 256, 256>>>(x, N0, N2, N3, N4);
    k_sagg<<<(E + 255) / 256, 256>>>(src, dst, E);

    // layer 1: conv (rank-1, exact) + pool -> g_a ; stats -> sc/sh[0]
    k_pool1<<<(N2 * 64 + 255) / 256, 256>>>(x, W1, b1, N0, N2);
    k_stats<<<64, 256>>>(N2, 0, g1, be1);

    // layer 2 (bn fused into gemm load)
    k_gemm<2><<<(N2 + 31) / 32, 256>>>(W2, b2, N2);
    k_econv<2><<<1024, 256>>>();
    k_pool<<<(N3 * 64 + 255) / 256, 256>>>(N2, N3, 2);
    k_stats<<<64, 256>>>(N3, 1, g2, be2);

    // layer 3
    k_gemm<3><<<(N3 + 31) / 32, 256>>>(W3, b3, N3);
    k_econv<3><<<512, 256>>>();
    k_pool<<<(N4 * 64 + 255) / 256, 256>>>(N3, N4, 3);
    k_stats<<<64, 256>>>(N4, 2, g3, be3);

    // layer 4
    k_gemm<4><<<(N4 + 31) / 32, 256>>>(W4, b4, N4);
    k_econv<4><<<128, 256>>>();
    k_pool<<<(N5 * 64 + 255) / 256, 256>>>(N4, N5, 3);
    k_stats<<<64, 256>>>(N5, 3, g4, be4);

    // head
    k_constrow<<<1, 32>>>(fcb1, fcW2, fcb2);
    k_fc<<<(N5 + 15) / 16, 128>>>(fcW1, fcb1, fcW2, fcb2, out, N5);
    long long fillN = (long long)(N0 - N5) * 10;
    k_fill<<<(int)((fillN + 255) / 256), 256>>>(out, N0, N5);
}

// round 11
// speedup vs baseline: 1.5860x; 1.0731x over previous
#include <cuda_runtime.h>

#define EPS 1e-5f

#define MAXN   100000
#define MAXN2  50000
#define MAXN3  25000
#define MAXN4  8340
#define MAXE   1600000
#define SPAD   32   // stat slot stride (floats) to spread LTS slices

// ---------------- scratch (static device globals; no allocation) ----------------
__device__ int    g_deg1[MAXN];
__device__ int    g_deg2[MAXN2];
__device__ int    g_deg3[MAXN3];
__device__ int    g_deg4[MAXN4];
__device__ float  g_dis1[MAXN];
__device__ float  g_dis2[MAXN2];
__device__ float  g_dis3[MAXN3];
__device__ float  g_dis4[MAXN4];
__device__ float  g_y[MAXN];
__device__ float  g_s[MAXN];
__device__ float  g_stat1[64 * SPAD];  // fused BN partial sums (padded slots)
__device__ float  g_stat2[64 * SPAD];
__device__ float  g_sc[4][64];
__device__ float  g_sh[4][64];
__device__ float  g_constrow[10];
__device__ int    g_cnt[3];
__device__ __align__(16) int2  g_e2[MAXE];
__device__ __align__(16) int2  g_e3[MAXE];
__device__ __align__(16) int2  g_e4[MAXE];
__device__ __align__(16) float g_a[MAXN2 * 64];
__device__ __align__(16) float g_xw[MAXN2 * 64];
__device__ __align__(16) float g_msg[MAXN2 * 64];

// ---------------- init (idempotent reset) ----------------
__global__ void k_init() {
    int i = blockIdx.x * blockDim.x + threadIdx.x;
    if (i < MAXN)  { g_deg1[i] = 0; g_s[i] = 0.f; }
    if (i < MAXN2) g_deg2[i] = 0;
    if (i < MAXN3) g_deg3[i] = 0;
    if (i < MAXN4) g_deg4[i] = 0;
    if (i < 3)     g_cnt[i] = 0;
    if (i < 64 * SPAD) { g_stat1[i] = 0.f; g_stat2[i] = 0.f; }
}

// ---------------- degree pass + edge compaction, 4 edges/thread ----------------
__global__ void k_deg(const int* __restrict__ src,
                      const int* __restrict__ dst, int E) {
    __shared__ int  sc[3];
    __shared__ int  sb[3];
    __shared__ int2 st[3][1024];
    int tid = threadIdx.x;
    if (tid < 3) sc[tid] = 0;
    __syncthreads();

    int base = (blockIdx.x * blockDim.x + tid) * 4;
    #pragma unroll
    for (int q = 0; q < 4; q++) {
        int e = base + q;
        if (e >= E) break;
        int s = src[e];
        int d = dst[e];
        if ((unsigned)s < MAXN && (unsigned)d < MAXN) {
            atomicAdd(&g_deg1[d], 1);
            if (((s | d) & 1) == 0) {
                int p = atomicAdd(&sc[0], 1);
                st[0][p] = make_int2(s >> 1, d >> 1);
                atomicAdd(&g_deg2[d >> 1], 1);
            }
            if (((s | d) & 3) == 0) {
                int p = atomicAdd(&sc[1], 1);
                st[1][p] = make_int2(s >> 2, d >> 2);
                atomicAdd(&g_deg3[d >> 2], 1);
            }
            if ((s % 12 == 0) && (d % 12 == 0)) {
                int p = atomicAdd(&sc[2], 1);
                st[2][p] = make_int2(s / 12, d / 12);
                atomicAdd(&g_deg4[d / 12], 1);
            }
        }
    }
    __syncthreads();
    if (tid < 3) sb[tid] = atomicAdd(&g_cnt[tid], sc[tid]);
    __syncthreads();
    #pragma unroll
    for (int l = 0; l < 3; l++) {
        int n = sc[l];
        int2* dstp = (l == 0) ? g_e2 : (l == 1) ? g_e3 : g_e4;
        int b = sb[l];
        for (int i = tid; i < n; i += blockDim.x) {
            int idx = b + i;
            if (idx < MAXE) dstp[idx] = st[l][i];
        }
    }
}

// ---------------- node pass ----------------
__global__ void k_node(const float* __restrict__ x, int N1, int N2, int N3, int N4) {
    int i = blockIdx.x * blockDim.x + threadIdx.x;
    if (i < N1) {
        float di = rsqrtf((float)g_deg1[i] + 1.f);
        g_dis1[i] = di;
        g_y[i] = di * x[i];
    }
    if (i < N2) g_dis2[i] = rsqrtf((float)g_deg2[i] + 1.f);
    if (i < N3) g_dis3[i] = rsqrtf((float)g_deg3[i] + 1.f);
    if (i < N4) g_dis4[i] = rsqrtf((float)g_deg4[i] + 1.f);
}

// ---------------- layer-1 scalar aggregation, 4 edges/thread ----------------
__global__ void k_sagg(const int* __restrict__ src,
                       const int* __restrict__ dst, int E) {
    int base = (blockIdx.x * blockDim.x + threadIdx.x) * 4;
    if (base + 3 < E) {
        int4 s4 = *(const int4*)(src + base);
        int4 d4 = *(const int4*)(dst + base);
        float v0 = ((unsigned)s4.x < MAXN) ? g_y[s4.x] : 0.f;
        float v1 = ((unsigned)s4.y < MAXN) ? g_y[s4.y] : 0.f;
        float v2 = ((unsigned)s4.z < MAXN) ? g_y[s4.z] : 0.f;
        float v3 = ((unsigned)s4.w < MAXN) ? g_y[s4.w] : 0.f;
        if ((unsigned)d4.x < MAXN) atomicAdd(&g_s[d4.x], v0);
        if ((unsigned)d4.y < MAXN) atomicAdd(&g_s[d4.y], v1);
        if ((unsigned)d4.z < MAXN) atomicAdd(&g_s[d4.z], v2);
        if ((unsigned)d4.w < MAXN) atomicAdd(&g_s[d4.w], v3);
    } else {
        for (int e = base; e < E; e++) {
            int s = src[e], d = dst[e];
            if ((unsigned)s < MAXN && (unsigned)d < MAXN)
                atomicAdd(&g_s[d], g_y[s]);
        }
    }
}

// ---------------- shared helper: block stat reduce + atomic flush ----------------
__device__ __forceinline__ void stat_flush(float ls1, float ls2, int tid) {
    __shared__ float sh1[256], sh2[256];
    sh1[tid] = ls1; sh2[tid] = ls2;
    __syncthreads();
    if (tid < 64) {
        float a1 = sh1[tid] + sh1[tid + 64] + sh1[tid + 128] + sh1[tid + 192];
        float a2 = sh2[tid] + sh2[tid + 64] + sh2[tid + 128] + sh2[tid + 192];
        atomicAdd(&g_stat1[tid * SPAD], a1);
        atomicAdd(&g_stat2[tid * SPAD], a2);
    }
}

// ---------------- pool1 + fused stats: grid-stride ----------------
__global__ void k_pool1(const float* __restrict__ x, const float* __restrict__ W1,
                        const float* __restrict__ b1, int N1, int N2) {
    int tid = threadIdx.x;
    float ls1 = 0.f, ls2 = 0.f;
    int total = N2 * 64;
    int step = gridDim.x * blockDim.x;
    for (int idx = blockIdx.x * blockDim.x + tid; idx < total; idx += step) {
        int p = idx >> 6, c = idx & 63;
        int i0 = 2 * p;
        float d0 = g_dis1[i0];
        float t = d0 * (g_s[i0] + d0 * x[i0]);
        int i1 = i0 + 1;
        if (i1 < N1) {
            float d1 = g_dis1[i1];
            t += d1 * (g_s[i1] + d1 * x[i1]);
        }
        float val = 0.5f * t * W1[c] + b1[c];
        g_a[idx] = val;
        ls1 += val; ls2 += val * val;
    }
    stat_flush(ls1, ls2, tid);
}

// ---------------- BN finalize: sums -> sc/sh, reset slots ----------------
__global__ void k_bnfin(int N, int l, const float* __restrict__ g,
                        const float* __restrict__ be) {
    int c = threadIdx.x;  // 64 threads
    float s1 = g_stat1[c * SPAD];
    float s2 = g_stat2[c * SPAD];
    g_stat1[c * SPAD] = 0.f;
    g_stat2[c * SPAD] = 0.f;
    float m = s1 / (float)N;
    float v = s2 / (float)N - m * m;
    float sc = rsqrtf(v + EPS) * g[c];
    g_sc[l][c] = sc;
    g_sh[l][c] = be[c] - m * sc;
}

// ---------------- fused BN-ReLU + GEMM + self-loop/bias epilogue ----------------
template <int L>
__global__ void k_gemm(const float* __restrict__ W, const float* __restrict__ b, int N) {
    __shared__ float Ws[64 * 64];
    __shared__ float xs[32][65];
    const float* dis = (L == 2) ? g_dis2 : (L == 3) ? g_dis3 : g_dis4;
    int tid = threadIdx.x;
    for (int i = tid; i < 4096; i += 256) Ws[i] = W[i];
    int row0 = blockIdx.x * 32;
    for (int i = tid; i < 2048; i += 256) {
        int r = i >> 6, k = i & 63;
        int row = row0 + r;
        float v = 0.f;
        if (row < N)
            v = fmaxf(0.f, fmaf(g_a[(size_t)row * 64 + k], g_sc[L - 2][k], g_sh[L - 2][k]));
        xs[r][k] = v;
    }
    __syncthreads();
    int c = tid & 63;
    int rq = tid >> 6;
    float acc[8] = {0.f, 0.f, 0.f, 0.f, 0.f, 0.f, 0.f, 0.f};
    #pragma unroll
    for (int k = 0; k < 64; k++) {
        float w = Ws[k * 64 + c];
        #pragma unroll
        for (int j = 0; j < 8; j++) acc[j] = fmaf(xs[rq * 8 + j][k], w, acc[j]);
    }
    float bc = b[c];
    #pragma unroll
    for (int j = 0; j < 8; j++) {
        int row = row0 + rq * 8 + j;
        if (row < N) {
            float di = dis[row];
            g_xw[(size_t)row * 64 + c] = acc[j];
            g_msg[(size_t)row * 64 + c] = fmaf(di * di, acc[j], bc);
        }
    }
}

// ---------------- sparse aggregation over compacted lists, vector red -------------
template <int L>
__global__ void k_econv() {
    const int2*  el  = (L == 2) ? g_e2   : (L == 3) ? g_e3   : g_e4;
    const float* dis = (L == 2) ? g_dis2 : (L == 3) ? g_dis3 : g_dis4;
    int cnt = g_cnt[L - 2];
    if (cnt > MAXE) cnt = MAXE;
    int gtid = blockIdx.x * blockDim.x + threadIdx.x;
    int lane = gtid & 15;
    int grp  = gtid >> 4;
    int step = (gridDim.x * blockDim.x) >> 4;
    for (int e = grp; e < cnt; e += step) {
        int2 ed = el[e];
        float coef = dis[ed.x] * dis[ed.y];
        float4 v = *((const float4*)(g_xw + (size_t)ed.x * 64) + lane);
        float4* pd = (float4*)(g_msg + (size_t)ed.y * 64) + lane;
        asm volatile("red.global.add.v4.f32 [%0], {%1,%2,%3,%4};"
                     :: "l"(pd), "f"(v.x * coef), "f"(v.y * coef),
                        "f"(v.z * coef), "f"(v.w * coef)
                     : "memory");
    }
}

// ---------------- pool + fused stats: grid-stride ----------------
__global__ void k_pool(int Nin, int Nout, int S) {
    int tid = threadIdx.x;
    float ls1 = 0.f, ls2 = 0.f;
    int total = Nout * 64;
    int step = gridDim.x * blockDim.x;
    float inv = 1.f / (float)S;
    for (int idx = blockIdx.x * blockDim.x + tid; idx < total; idx += step) {
        int p = idx >> 6, c = idx & 63;
        float acc = 0.f;
        int base = p * S;
        for (int q = 0; q < S; q++) {
            int r = base + q;
            if (r < Nin) acc += g_msg[(size_t)r * 64 + c];
        }
        float val = acc * inv;
        g_a[idx] = val;
        ls1 += val; ls2 += val * val;
    }
    stat_flush(ls1, ls2, tid);
}

// ---------------- constant output row for padded nodes ----------------
__global__ void k_constrow(const float* __restrict__ fcb1,
                           const float* __restrict__ fcW2,
                           const float* __restrict__ fcb2) {
    int c = threadIdx.x;
    if (c < 10) {
        float acc = fcb2[c];
        for (int k = 0; k < 128; k++)
            acc = fmaf(fmaxf(0.f, fcb1[k]), fcW2[k * 10 + c], acc);
        g_constrow[c] = acc;
    }
}

// ---------------- FC head: applies layer-4 BN (l=3) on the fly --------------------
__global__ void k_fc(const float* __restrict__ fcW1, const float* __restrict__ fcb1,
                     const float* __restrict__ fcW2, const float* __restrict__ fcb2,
                     float* __restrict__ out, int N5) {
    __shared__ float W1s[64 * 128];
    __shared__ float W2s[128 * 10];
    __shared__ float xr[64];
    __shared__ float hb[128];
    int tid = threadIdx.x;  // 128 threads
    for (int i = tid; i < 8192; i += 128) W1s[i] = fcW1[i];
    for (int i = tid; i < 1280; i += 128) W2s[i] = fcW2[i];
    __syncthreads();
    int r0 = blockIdx.x * 16;
    for (int rr = 0; rr < 16; rr++) {
        int row = r0 + rr;
        if (row >= N5) break;
        if (tid < 64)
            xr[tid] = fmaxf(0.f, fmaf(g_a[(size_t)row * 64 + tid],
                                      g_sc[3][tid], g_sh[3][tid]));
        __syncthreads();
        float h = fcb1[tid];
        #pragma unroll
        for (int k = 0; k < 64; k++) h = fmaf(xr[k], W1s[k * 128 + tid], h);
        hb[tid] = fmaxf(0.f, h);
        __syncthreads();
        if (tid < 10) {
            float acc = fcb2[tid];
            #pragma unroll 8
            for (int k = 0; k < 128; k++) acc = fmaf(hb[k], W2s[k * 10 + tid], acc);
            out[(size_t)row * 10 + tid] = acc;
        }
        __syncthreads();
    }
}

// ---------------- constant fill for padded rows ----------------
__global__ void k_fill(float* __restrict__ out, int N0, int N5) {
    long long total = (long long)(N0 - N5) * 10;
    long long idx = (long long)blockIdx.x * blockDim.x + threadIdx.x;
    if (idx < total) {
        int j = (int)(idx % 10);
        long long r = N5 + idx / 10;
        out[r * 10 + j] = g_constrow[j];
    }
}

// ---------------- launch ----------------
extern "C" void kernel_launch(void* const* d_in, const int* in_sizes, int n_in,
                              void* d_out, int out_size) {
    const float* x    = (const float*)d_in[0];
    const float* W1   = (const float*)d_in[1];
    const float* b1   = (const float*)d_in[2];
    const float* g1   = (const float*)d_in[3];
    const float* be1  = (const float*)d_in[4];
    const float* W2   = (const float*)d_in[5];
    const float* b2   = (const float*)d_in[6];
    const float* g2   = (const float*)d_in[7];
    const float* be2  = (const float*)d_in[8];
    const float* W3   = (const float*)d_in[9];
    const float* b3   = (const float*)d_in[10];
    const float* g3   = (const float*)d_in[11];
    const float* be3  = (const float*)d_in[12];
    const float* W4   = (const float*)d_in[13];
    const float* b4   = (const float*)d_in[14];
    const float* g4   = (const float*)d_in[15];
    const float* be4  = (const float*)d_in[16];
    const float* fcW1 = (const float*)d_in[17];
    const float* fcb1 = (const float*)d_in[18];
    const float* fcW2 = (const float*)d_in[19];
    const float* fcb2 = (const float*)d_in[20];
    const int* src = (const int*)d_in[21];  // JAX x64 disabled: int32
    const int* dst = (const int*)d_in[22];

    int N0 = in_sizes[0];
    if (N0 > MAXN) N0 = MAXN;
    int E  = in_sizes[21];
    if (E > MAXE) E = MAXE;
    int N2 = (N0 + 1) / 2;
    int N3 = (N2 + 1) / 2;
    int N4 = (N3 + 2) / 3;
    int N5 = (N4 + 2) / 3;
    float* out = (float*)d_out;

    k_init<<<(MAXN + 255) / 256, 256>>>();
    k_deg<<<(E + 1023) / 1024, 256>>>(src, dst, E);
    k_node<<<(N0 + 255) / 256, 256>>>(x, N0, N2, N3, N4);
    k_sagg<<<(E + 1023) / 1024, 256>>>(src, dst, E);

    // layer 1
    k_pool1<<<592, 256>>>(x, W1, b1, N0, N2);
    k_bnfin<<<1, 64>>>(N2, 0, g1, be1);

    // layer 2
    k_gemm<2><<<(N2 + 31) / 32, 256>>>(W2, b2, N2);
    k_econv<2><<<1024, 256>>>();
    k_pool<<<296, 256>>>(N2, N3, 2);
    k_bnfin<<<1, 64>>>(N3, 1, g2, be2);

    // layer 3
    k_gemm<3><<<(N3 + 31) / 32, 256>>>(W3, b3, N3);
    k_econv<3><<<512, 256>>>();
    k_pool<<<148, 256>>>(N3, N4, 3);
    k_bnfin<<<1, 64>>>(N4, 2, g3, be3);

    // layer 4
    k_gemm<4><<<(N4 + 31) / 32, 256>>>(W4, b4, N4);
    k_econv<4><<<128, 256>>>();
    k_pool<<<64, 256>>>(N4, N5, 3);
    k_bnfin<<<1, 64>>>(N5, 3, g4, be4);

    // head
    k_constrow<<<1, 32>>>(fcb1, fcW2, fcb2);
    k_fc<<<(N5 + 15) / 16, 128>>>(fcW1, fcb1, fcW2, fcb2, out, N5);
    long long fillN = (long long)(N0 - N5) * 10;
    k_fill<<<(int)((fillN + 255) / 256), 256>>>(out, N0, N5);
}